// round 2
// baseline (speedup 1.0000x reference)
#include <cuda_runtime.h>
#include <math.h>

// Problem constants
#define B_     2
#define T_     16
#define S_     128
#define D_     512
#define H_     16
#define DH_    64
#define INNER_ 1024
#define NTOK   2048    // T_*S_
#define MROWS  4096    // B_*NTOK

// Scratch (device globals; no allocation allowed in kernel_launch)
__device__ float g_Q[MROWS * INNER_];
__device__ float g_K[MROWS * INNER_];
__device__ float g_V[MROWS * INNER_];
__device__ float g_O[MROWS * INNER_];   // attention output, [m, h*64+d]
__device__ float g_P[MROWS * D_];       // output projection result

// ---------------------------------------------------------------------------
// Fused QKV GEMM: z = 0/1/2 selects (x,Wq)->Q, (x,Wk)->K, (y,Wv)->V.
// C[M,1024] = (A + pos) @ W. Tiles: 64x64, BK=16, 256 threads, 4x4 microtile.
// ---------------------------------------------------------------------------
__global__ void __launch_bounds__(256) qkv_gemm_kernel(
    const float* __restrict__ x, const float* __restrict__ y,
    const float* __restrict__ Wq, const float* __restrict__ Wk,
    const float* __restrict__ Wv,
    float* __restrict__ Q, float* __restrict__ K, float* __restrict__ V,
    const float* __restrict__ pos)
{
    __shared__ float As[64][16];
    __shared__ float Bs[16][64];

    int z = blockIdx.z;
    const float* A = (z == 2) ? y : x;
    const float* W = (z == 0) ? Wq : (z == 1) ? Wk : Wv;
    float* C = (z == 0) ? Q : (z == 1) ? K : V;

    int tid = threadIdx.x;
    int tx  = tid & 15;
    int ty  = tid >> 4;
    int m0  = blockIdx.y * 64;
    int n0  = blockIdx.x * 64;

    int arow = tid >> 2;
    int ak4  = (tid & 3) * 4;
    int brow = tid >> 4;
    int bcol = (tid & 15) * 4;

    const float* Arow = A + (size_t)(m0 + arow) * D_;
    int t = ((m0 + arow) & (NTOK - 1)) >> 7;      // temporal index
    const float* posrow = pos + t * D_;

    float acc[4][4];
#pragma unroll
    for (int r = 0; r < 4; r++)
#pragma unroll
        for (int c = 0; c < 4; c++) acc[r][c] = 0.f;

    for (int k0 = 0; k0 < D_; k0 += 16) {
        float4 a4 = *(const float4*)(Arow + k0 + ak4);
        float4 p4 = *(const float4*)(posrow + k0 + ak4);
        a4.x += p4.x; a4.y += p4.y; a4.z += p4.z; a4.w += p4.w;
        float4 b4 = *(const float4*)(W + (size_t)(k0 + brow) * INNER_ + n0 + bcol);

        __syncthreads();
        *(float4*)&As[arow][ak4] = a4;
        *(float4*)&Bs[brow][bcol] = b4;
        __syncthreads();

#pragma unroll
        for (int kk = 0; kk < 16; kk++) {
            float a[4];
#pragma unroll
            for (int r = 0; r < 4; r++) a[r] = As[ty * 4 + r][kk];
            float4 bv = *(float4*)&Bs[kk][tx * 4];
            float b[4] = {bv.x, bv.y, bv.z, bv.w};
#pragma unroll
            for (int r = 0; r < 4; r++)
#pragma unroll
                for (int c = 0; c < 4; c++) acc[r][c] += a[r] * b[c];
        }
    }

#pragma unroll
    for (int r = 0; r < 4; r++) {
        int m = m0 + ty * 4 + r;
        float4 o = make_float4(acc[r][0], acc[r][1], acc[r][2], acc[r][3]);
        *(float4*)(C + (size_t)m * INNER_ + n0 + tx * 4) = o;
    }
}

// ---------------------------------------------------------------------------
// Output projection GEMM: P[4096,512] = O[4096,1024] @ Wo + bo.
// Same tiling as above.
// ---------------------------------------------------------------------------
__global__ void __launch_bounds__(256) proj_gemm_kernel(
    const float* __restrict__ A, const float* __restrict__ W,
    float* __restrict__ C, const float* __restrict__ bias)
{
    __shared__ float As[64][16];
    __shared__ float Bs[16][64];

    int tid = threadIdx.x;
    int tx  = tid & 15;
    int ty  = tid >> 4;
    int m0  = blockIdx.y * 64;
    int n0  = blockIdx.x * 64;

    int arow = tid >> 2;
    int ak4  = (tid & 3) * 4;
    int brow = tid >> 4;
    int bcol = (tid & 15) * 4;

    const float* Arow = A + (size_t)(m0 + arow) * INNER_;

    float acc[4][4];
#pragma unroll
    for (int r = 0; r < 4; r++)
#pragma unroll
        for (int c = 0; c < 4; c++) acc[r][c] = 0.f;

    for (int k0 = 0; k0 < INNER_; k0 += 16) {
        float4 a4 = *(const float4*)(Arow + k0 + ak4);
        float4 b4 = *(const float4*)(W + (size_t)(k0 + brow) * D_ + n0 + bcol);

        __syncthreads();
        *(float4*)&As[arow][ak4] = a4;
        *(float4*)&Bs[brow][bcol] = b4;
        __syncthreads();

#pragma unroll
        for (int kk = 0; kk < 16; kk++) {
            float a[4];
#pragma unroll
            for (int r = 0; r < 4; r++) a[r] = As[ty * 4 + r][kk];
            float4 bv = *(float4*)&Bs[kk][tx * 4];
            float b[4] = {bv.x, bv.y, bv.z, bv.w};
#pragma unroll
            for (int r = 0; r < 4; r++)
#pragma unroll
                for (int c = 0; c < 4; c++) acc[r][c] += a[r] * b[c];
        }
    }

#pragma unroll
    for (int r = 0; r < 4; r++) {
        int m = m0 + ty * 4 + r;
        const float* bb = bias + n0 + tx * 4;
        float4 o = make_float4(acc[r][0] + bb[0], acc[r][1] + bb[1],
                               acc[r][2] + bb[2], acc[r][3] + bb[3]);
        *(float4*)(C + (size_t)m * D_ + n0 + tx * 4) = o;
    }
}

// ---------------------------------------------------------------------------
// RoPE over flattened token index, in-place on Q and K.
// One thread per (m, head, freq-pair).
// ---------------------------------------------------------------------------
__global__ void __launch_bounds__(256) rope_kernel(float* __restrict__ Q,
                                                   float* __restrict__ Kt)
{
    int gid = blockIdx.x * blockDim.x + threadIdx.x;   // [0, MROWS*512)
    int m  = gid >> 9;
    int r  = gid & 511;
    int h  = r >> 5;
    int dd = r & 31;
    int i  = m & (NTOK - 1);

    // inv_freq = 10000^(-dd/32) = 2^(-(dd/32)*log2(10000))
    float inv = exp2f(-(float)dd * (13.287712379549449f / 32.0f));
    float f = (float)i * inv;
    float c = cosf(f), s = sinf(f);

    size_t base = (size_t)m * INNER_ + h * DH_ + dd;
    float a = Q[base], b2 = Q[base + 32];
    Q[base]      = a * c - b2 * s;
    Q[base + 32] = b2 * c + a * s;
    a = Kt[base]; b2 = Kt[base + 32];
    Kt[base]      = a * c - b2 * s;
    Kt[base + 32] = b2 * c + a * s;
}

// ---------------------------------------------------------------------------
// Flash-style attention. Block = (b, h, ti): 128 threads = 128 query rows of
// one temporal block. Masked temporal key blocks skipped entirely.
// Online softmax with lazy rescale; K/V staged 64 keys at a time in smem.
// ---------------------------------------------------------------------------
__global__ void __launch_bounds__(128) attn_kernel(
    const float* __restrict__ Q, const float* __restrict__ K,
    const float* __restrict__ V, const int* __restrict__ tmask,
    float* __restrict__ O)
{
    __shared__ float ks[64][64];
    __shared__ float vs[64][64];

    int blk = blockIdx.x;                 // ((b*H + h)*T + ti)
    int ti  = blk % T_;
    int bh  = blk / T_;
    int h   = bh % H_;
    int b   = bh / H_;
    int tid = threadIdx.x;
    int i   = ti * S_ + tid;

    const float* qp = Q + ((size_t)(b * NTOK + i)) * INNER_ + h * DH_;
    float q[64];
#pragma unroll
    for (int d = 0; d < 64; d += 4) {
        float4 t4 = *(const float4*)(qp + d);
        q[d] = t4.x; q[d + 1] = t4.y; q[d + 2] = t4.z; q[d + 3] = t4.w;
    }

    float mmax = -1e30f, l = 0.f;
    float acc[64];
#pragma unroll
    for (int d = 0; d < 64; d++) acc[d] = 0.f;

    for (int tj = 0; tj < T_; tj++) {
        if (tmask[(b * T_ + ti) * T_ + tj] == 0) continue;   // block-uniform
        for (int half = 0; half < 2; half++) {
            int j0 = tj * S_ + half * 64;
            const float* kb = K + ((size_t)(b * NTOK + j0)) * INNER_ + h * DH_;
            const float* vb = V + ((size_t)(b * NTOK + j0)) * INNER_ + h * DH_;
            __syncthreads();
            for (int u = tid; u < 64 * 16; u += 128) {
                int row = u >> 4, d4 = u & 15;
                ((float4*)ks[row])[d4] = *(const float4*)(kb + (size_t)row * INNER_ + d4 * 4);
                ((float4*)vs[row])[d4] = *(const float4*)(vb + (size_t)row * INNER_ + d4 * 4);
            }
            __syncthreads();

            for (int j = 0; j < 64; j++) {
                float s = 0.f;
#pragma unroll
                for (int d = 0; d < 64; d++) s += q[d] * ks[j][d];
                s *= 0.125f;                      // DIM_HEAD^-0.5
                if (s > mmax) {                   // lazy rescale
                    float corr = __expf(mmax - s);
                    l *= corr;
#pragma unroll
                    for (int d = 0; d < 64; d++) acc[d] *= corr;
                    mmax = s;
                }
                float p = __expf(s - mmax);
                l += p;
#pragma unroll
                for (int d = 0; d < 64; d++) acc[d] += p * vs[j][d];
            }
        }
    }

    float invl = (l > 0.f) ? (1.f / l) : 0.f;
    float* op = O + ((size_t)(b * NTOK + i)) * INNER_ + h * DH_;
#pragma unroll
    for (int d = 0; d < 64; d += 4) {
        float4 o4 = make_float4(acc[d] * invl, acc[d + 1] * invl,
                                acc[d + 2] * invl, acc[d + 3] * invl);
        *(float4*)(op + d) = o4;
    }
}

// ---------------------------------------------------------------------------
// Gate: per row of P[4096,512]: g = sigmoid(dot(row, gate_w) + gate_b);
// out = row * g.
// ---------------------------------------------------------------------------
__global__ void __launch_bounds__(128) gate_kernel(
    const float* __restrict__ P, const float* __restrict__ gw,
    const float* __restrict__ gb, float* __restrict__ out)
{
    int m = blockIdx.x;
    int tid = threadIdx.x;
    const float* row = P + (size_t)m * D_;

    float v[4];
    float part = 0.f;
#pragma unroll
    for (int r = 0; r < 4; r++) {
        int j = tid + r * 128;
        v[r] = row[j];
        part += v[r] * gw[j];
    }
#pragma unroll
    for (int off = 16; off; off >>= 1)
        part += __shfl_xor_sync(0xffffffffu, part, off);

    __shared__ float red[4];
    if ((tid & 31) == 0) red[tid >> 5] = part;
    __syncthreads();
    float tot = red[0] + red[1] + red[2] + red[3] + gb[0];
    float gate = 1.f / (1.f + __expf(-tot));

    float* orow = out + (size_t)m * D_;
#pragma unroll
    for (int r = 0; r < 4; r++) {
        int j = tid + r * 128;
        orow[j] = v[r] * gate;
    }
}

// ---------------------------------------------------------------------------
extern "C" void kernel_launch(void* const* d_in, const int* in_sizes, int n_in,
                              void* d_out, int out_size)
{
    (void)in_sizes; (void)n_in; (void)out_size;
    const float* x     = (const float*)d_in[0];
    const float* y     = (const float*)d_in[1];
    const int*   tmask = (const int*)  d_in[2];
    const float* Wq    = (const float*)d_in[3];
    const float* Wk    = (const float*)d_in[4];
    const float* Wv    = (const float*)d_in[5];
    const float* Wo    = (const float*)d_in[6];
    const float* bo    = (const float*)d_in[7];
    const float* pos   = (const float*)d_in[8];
    const float* gw    = (const float*)d_in[9];
    const float* gb    = (const float*)d_in[10];
    float* out = (float*)d_out;

    float *Qp, *Kp, *Vp, *Op, *Pp;
    cudaGetSymbolAddress((void**)&Qp, g_Q);
    cudaGetSymbolAddress((void**)&Kp, g_K);
    cudaGetSymbolAddress((void**)&Vp, g_V);
    cudaGetSymbolAddress((void**)&Op, g_O);
    cudaGetSymbolAddress((void**)&Pp, g_P);

    dim3 blk(256);
    dim3 gq(INNER_ / 64, MROWS / 64, 3);   // 16 x 64 x 3 (Q, K, V)
    qkv_gemm_kernel<<<gq, blk>>>(x, y, Wq, Wk, Wv, Qp, Kp, Vp, pos);

    rope_kernel<<<(MROWS * 512) / 256, 256>>>(Qp, Kp);

    attn_kernel<<<B_ * H_ * T_, 128>>>(Qp, Kp, Vp, tmask, Op);

    dim3 gp(D_ / 64, MROWS / 64);          // 8 x 64
    proj_gemm_kernel<<<gp, blk>>>(Op, Wo, Pp, bo);

    gate_kernel<<<MROWS, 128>>>(Pp, gw, gb, out);
}

// round 4
// speedup vs baseline: 1.2830x; 1.2830x over previous
#include <cuda_runtime.h>
#include <math.h>
#include <stdint.h>

// Problem constants
#define B_     2
#define T_     16
#define S_     128
#define D_     512
#define H_     16
#define DH_    64
#define INNER_ 1024
#define NTOK   2048    // T_*S_
#define MROWS  4096    // B_*NTOK

// Scratch (device globals; no allocation allowed in kernel_launch)
__device__ float g_Q[MROWS * INNER_];
__device__ float g_K[MROWS * INNER_];
__device__ float g_V[MROWS * INNER_];
__device__ float g_O[MROWS * INNER_];   // attention output
__device__ float g_P[MROWS * D_];       // output projection result

// ---------------------------------------------------------------------------
// tf32 helpers
// ---------------------------------------------------------------------------
__device__ __forceinline__ uint32_t f2tf32(float f) {
    uint32_t u;
    asm("cvt.rna.tf32.f32 %0, %1;" : "=r"(u) : "f"(f));
    return u;
}

__device__ __forceinline__ void mma_tf32(float* c, const uint32_t* a,
                                         const uint32_t* b) {
    asm volatile(
        "mma.sync.aligned.m16n8k8.row.col.f32.tf32.tf32.f32 "
        "{%0,%1,%2,%3},{%4,%5,%6,%7},{%8,%9},{%0,%1,%2,%3};"
        : "+f"(c[0]), "+f"(c[1]), "+f"(c[2]), "+f"(c[3])
        : "r"(a[0]), "r"(a[1]), "r"(a[2]), "r"(a[3]), "r"(b[0]), "r"(b[1]));
}

// ---------------------------------------------------------------------------
// tf32 tensor-core GEMM. CTA tile 128x64, BK=32, 256 threads (8 warps, 4x2).
// QKV=true: blockIdx.z selects (x,Wq)->Q / (x,Wk)->K / (y,Wv)->V with fused
// pos_emb add on A. QKV=false: single GEMM with fused bias (output proj).
// Smem strides chosen conflict-free: As stride 36, Bs stride 72.
// ---------------------------------------------------------------------------
#define AS_STRIDE 36
#define BS_STRIDE 72

template<int KDIM, int NDIM, bool QKV>
__global__ void __launch_bounds__(256) gemm_tf32_kernel(
    const float* __restrict__ x, const float* __restrict__ y,
    const float* __restrict__ W0, const float* __restrict__ W1,
    const float* __restrict__ W2,
    float* __restrict__ C0, float* __restrict__ C1, float* __restrict__ C2,
    const float* __restrict__ pos, const float* __restrict__ bias)
{
    __shared__ uint32_t As[128 * AS_STRIDE];
    __shared__ uint32_t Bs[32 * BS_STRIDE];

    const float* A;
    const float* W;
    float* C;
    if (QKV) {
        int z = blockIdx.z;
        A = (z == 2) ? y : x;
        W = (z == 0) ? W0 : (z == 1) ? W1 : W2;
        C = (z == 0) ? C0 : (z == 1) ? C1 : C2;
    } else {
        A = x; W = W0; C = C0;
    }

    int tid  = threadIdx.x;
    int lane = tid & 31;
    int wid  = tid >> 5;
    int warpM = wid >> 1;          // 0..3
    int warpN = wid & 1;           // 0..1
    int m0 = blockIdx.y * 128;
    int n0 = blockIdx.x * 64;

    // A-tile loads: 4 float4 per thread over 128x32
    int aIdx[4], aRow[4], aCol[4];
#pragma unroll
    for (int i = 0; i < 4; i++) {
        aIdx[i] = tid + i * 256;
        aRow[i] = aIdx[i] >> 3;
        aCol[i] = (aIdx[i] & 7) * 4;
    }
    // B-tile loads: 2 float4 per thread over 32x64
    int bRow[2], bCol[2];
#pragma unroll
    for (int i = 0; i < 2; i++) {
        int idx = tid + i * 256;
        bRow[i] = idx >> 4;
        bCol[i] = (idx & 15) * 4;
    }

    float acc[2][4][4];
#pragma unroll
    for (int mt = 0; mt < 2; mt++)
#pragma unroll
        for (int nt = 0; nt < 4; nt++)
#pragma unroll
            for (int e = 0; e < 4; e++) acc[mt][nt][e] = 0.f;

    uint32_t aReg[4][4];
    uint32_t bReg[2][4];

    // prologue load (k0 = 0)
#pragma unroll
    for (int i = 0; i < 4; i++) {
        float4 a4 = *(const float4*)(A + (size_t)(m0 + aRow[i]) * KDIM + aCol[i]);
        if (QKV) {
            int t = ((m0 + aRow[i]) & (NTOK - 1)) >> 7;
            float4 p4 = *(const float4*)(pos + t * D_ + aCol[i]);
            a4.x += p4.x; a4.y += p4.y; a4.z += p4.z; a4.w += p4.w;
        }
        aReg[i][0] = f2tf32(a4.x); aReg[i][1] = f2tf32(a4.y);
        aReg[i][2] = f2tf32(a4.z); aReg[i][3] = f2tf32(a4.w);
    }
#pragma unroll
    for (int i = 0; i < 2; i++) {
        float4 b4 = *(const float4*)(W + (size_t)bRow[i] * NDIM + n0 + bCol[i]);
        bReg[i][0] = f2tf32(b4.x); bReg[i][1] = f2tf32(b4.y);
        bReg[i][2] = f2tf32(b4.z); bReg[i][3] = f2tf32(b4.w);
    }

    for (int k0 = 0; k0 < KDIM; k0 += 32) {
        __syncthreads();
#pragma unroll
        for (int i = 0; i < 4; i++)
            *(uint4*)&As[aRow[i] * AS_STRIDE + aCol[i]] =
                make_uint4(aReg[i][0], aReg[i][1], aReg[i][2], aReg[i][3]);
#pragma unroll
        for (int i = 0; i < 2; i++)
            *(uint4*)&Bs[bRow[i] * BS_STRIDE + bCol[i]] =
                make_uint4(bReg[i][0], bReg[i][1], bReg[i][2], bReg[i][3]);
        __syncthreads();

        int kn = k0 + 32;
        if (kn < KDIM) {
#pragma unroll
            for (int i = 0; i < 4; i++) {
                float4 a4 = *(const float4*)(A + (size_t)(m0 + aRow[i]) * KDIM + kn + aCol[i]);
                if (QKV) {
                    int t = ((m0 + aRow[i]) & (NTOK - 1)) >> 7;
                    float4 p4 = *(const float4*)(pos + t * D_ + kn + aCol[i]);
                    a4.x += p4.x; a4.y += p4.y; a4.z += p4.z; a4.w += p4.w;
                }
                aReg[i][0] = f2tf32(a4.x); aReg[i][1] = f2tf32(a4.y);
                aReg[i][2] = f2tf32(a4.z); aReg[i][3] = f2tf32(a4.w);
            }
#pragma unroll
            for (int i = 0; i < 2; i++) {
                float4 b4 = *(const float4*)(W + (size_t)(kn + bRow[i]) * NDIM + n0 + bCol[i]);
                bReg[i][0] = f2tf32(b4.x); bReg[i][1] = f2tf32(b4.y);
                bReg[i][2] = f2tf32(b4.z); bReg[i][3] = f2tf32(b4.w);
            }
        }

#pragma unroll
        for (int ks = 0; ks < 4; ks++) {
            uint32_t af[2][4];
            uint32_t bf[4][2];
#pragma unroll
            for (int mt = 0; mt < 2; mt++) {
                int rb = warpM * 32 + mt * 16 + (lane >> 2);
                int c0 = ks * 8 + (lane & 3);
                af[mt][0] = As[rb * AS_STRIDE + c0];
                af[mt][1] = As[(rb + 8) * AS_STRIDE + c0];
                af[mt][2] = As[rb * AS_STRIDE + c0 + 4];
                af[mt][3] = As[(rb + 8) * AS_STRIDE + c0 + 4];
            }
#pragma unroll
            for (int nt = 0; nt < 4; nt++) {
                int col = warpN * 32 + nt * 8 + (lane >> 2);
                int r = ks * 8 + (lane & 3);
                bf[nt][0] = Bs[r * BS_STRIDE + col];
                bf[nt][1] = Bs[(r + 4) * BS_STRIDE + col];
            }
#pragma unroll
            for (int mt = 0; mt < 2; mt++)
#pragma unroll
                for (int nt = 0; nt < 4; nt++)
                    mma_tf32(acc[mt][nt], af[mt], bf[nt]);
        }
    }

    // Epilogue: C fragment c0/c1 at (row, 2c), c2/c3 at (row+8, 2c)
#pragma unroll
    for (int mt = 0; mt < 2; mt++) {
#pragma unroll
        for (int nt = 0; nt < 4; nt++) {
            int row = m0 + warpM * 32 + mt * 16 + (lane >> 2);
            int col = n0 + warpN * 32 + nt * 8 + 2 * (lane & 3);
            float b0 = 0.f, b1 = 0.f;
            if (!QKV) { b0 = bias[col]; b1 = bias[col + 1]; }
            *(float2*)(C + (size_t)row * NDIM + col) =
                make_float2(acc[mt][nt][0] + b0, acc[mt][nt][1] + b1);
            *(float2*)(C + (size_t)(row + 8) * NDIM + col) =
                make_float2(acc[mt][nt][2] + b0, acc[mt][nt][3] + b1);
        }
    }
}

// ---------------------------------------------------------------------------
// RoPE over flattened token index, in-place on Q and K.
// ---------------------------------------------------------------------------
__global__ void __launch_bounds__(256) rope_kernel(float* __restrict__ Q,
                                                   float* __restrict__ Kt)
{
    int gid = blockIdx.x * blockDim.x + threadIdx.x;   // [0, MROWS*512)
    int m  = gid >> 9;
    int r  = gid & 511;
    int h  = r >> 5;
    int dd = r & 31;
    int i  = m & (NTOK - 1);

    float inv = exp2f(-(float)dd * (13.287712379549449f / 32.0f));
    float f = (float)i * inv;
    float c = cosf(f), s = sinf(f);

    size_t base = (size_t)m * INNER_ + h * DH_ + dd;
    float a = Q[base], b2 = Q[base + 32];
    Q[base]      = a * c - b2 * s;
    Q[base + 32] = b2 * c + a * s;
    a = Kt[base]; b2 = Kt[base + 32];
    Kt[base]      = a * c - b2 * s;
    Kt[base + 32] = b2 * c + a * s;
}

// ---------------------------------------------------------------------------
// Flash-style attention (SIMT). Block = (b, h, ti): 128 threads = 128 query
// rows. Masked temporal key blocks skipped entirely. Online softmax.
// ---------------------------------------------------------------------------
__global__ void __launch_bounds__(128) attn_kernel(
    const float* __restrict__ Q, const float* __restrict__ K,
    const float* __restrict__ V, const int* __restrict__ tmask,
    float* __restrict__ O)
{
    __shared__ float ks[64][64];
    __shared__ float vs[64][64];

    int blk = blockIdx.x;                 // ((b*H + h)*T + ti)
    int ti  = blk % T_;
    int bh  = blk / T_;
    int h   = bh % H_;
    int b   = bh / H_;
    int tid = threadIdx.x;
    int i   = ti * S_ + tid;

    const float* qp = Q + ((size_t)(b * NTOK + i)) * INNER_ + h * DH_;
    float q[64];
#pragma unroll
    for (int d = 0; d < 64; d += 4) {
        float4 t4 = *(const float4*)(qp + d);
        q[d] = t4.x; q[d + 1] = t4.y; q[d + 2] = t4.z; q[d + 3] = t4.w;
    }

    float mmax = -1e30f, l = 0.f;
    float acc[64];
#pragma unroll
    for (int d = 0; d < 64; d++) acc[d] = 0.f;

    for (int tj = 0; tj < T_; tj++) {
        if (tmask[(b * T_ + ti) * T_ + tj] == 0) continue;
        for (int half = 0; half < 2; half++) {
            int j0 = tj * S_ + half * 64;
            const float* kb = K + ((size_t)(b * NTOK + j0)) * INNER_ + h * DH_;
            const float* vb = V + ((size_t)(b * NTOK + j0)) * INNER_ + h * DH_;
            __syncthreads();
            for (int u = tid; u < 64 * 16; u += 128) {
                int row = u >> 4, d4 = u & 15;
                ((float4*)ks[row])[d4] = *(const float4*)(kb + (size_t)row * INNER_ + d4 * 4);
                ((float4*)vs[row])[d4] = *(const float4*)(vb + (size_t)row * INNER_ + d4 * 4);
            }
            __syncthreads();

            for (int j = 0; j < 64; j++) {
                float s = 0.f;
#pragma unroll
                for (int d = 0; d < 64; d++) s += q[d] * ks[j][d];
                s *= 0.125f;
                if (s > mmax) {
                    float corr = __expf(mmax - s);
                    l *= corr;
#pragma unroll
                    for (int d = 0; d < 64; d++) acc[d] *= corr;
                    mmax = s;
                }
                float p = __expf(s - mmax);
                l += p;
#pragma unroll
                for (int d = 0; d < 64; d++) acc[d] += p * vs[j][d];
            }
        }
    }

    float invl = (l > 0.f) ? (1.f / l) : 0.f;
    float* op = O + ((size_t)(b * NTOK + i)) * INNER_ + h * DH_;
#pragma unroll
    for (int d = 0; d < 64; d += 4) {
        float4 o4 = make_float4(acc[d] * invl, acc[d + 1] * invl,
                                acc[d + 2] * invl, acc[d + 3] * invl);
        *(float4*)(op + d) = o4;
    }
}

// ---------------------------------------------------------------------------
// Gate: per row of P[4096,512]: g = sigmoid(dot(row, gate_w) + gate_b).
// ---------------------------------------------------------------------------
__global__ void __launch_bounds__(128) gate_kernel(
    const float* __restrict__ P, const float* __restrict__ gw,
    const float* __restrict__ gb, float* __restrict__ out)
{
    int m = blockIdx.x;
    int tid = threadIdx.x;
    const float* row = P + (size_t)m * D_;

    float v[4];
    float part = 0.f;
#pragma unroll
    for (int r = 0; r < 4; r++) {
        int j = tid + r * 128;
        v[r] = row[j];
        part += v[r] * gw[j];
    }
#pragma unroll
    for (int off = 16; off; off >>= 1)
        part += __shfl_xor_sync(0xffffffffu, part, off);

    __shared__ float red[4];
    if ((tid & 31) == 0) red[tid >> 5] = part;
    __syncthreads();
    float tot = red[0] + red[1] + red[2] + red[3] + gb[0];
    float gate = 1.f / (1.f + __expf(-tot));

    float* orow = out + (size_t)m * D_;
#pragma unroll
    for (int r = 0; r < 4; r++) {
        int j = tid + r * 128;
        orow[j] = v[r] * gate;
    }
}

// ---------------------------------------------------------------------------
extern "C" void kernel_launch(void* const* d_in, const int* in_sizes, int n_in,
                              void* d_out, int out_size)
{
    (void)in_sizes; (void)n_in; (void)out_size;
    const float* x     = (const float*)d_in[0];
    const float* y     = (const float*)d_in[1];
    const int*   tmask = (const int*)  d_in[2];
    const float* Wq    = (const float*)d_in[3];
    const float* Wk    = (const float*)d_in[4];
    const float* Wv    = (const float*)d_in[5];
    const float* Wo    = (const float*)d_in[6];
    const float* bo    = (const float*)d_in[7];
    const float* pos   = (const float*)d_in[8];
    const float* gw    = (const float*)d_in[9];
    const float* gb    = (const float*)d_in[10];
    float* out = (float*)d_out;

    float *Qp, *Kp, *Vp, *Op, *Pp;
    cudaGetSymbolAddress((void**)&Qp, g_Q);
    cudaGetSymbolAddress((void**)&Kp, g_K);
    cudaGetSymbolAddress((void**)&Vp, g_V);
    cudaGetSymbolAddress((void**)&Op, g_O);
    cudaGetSymbolAddress((void**)&Pp, g_P);

    // QKV: C[4096,1024] = (A+pos)[4096,512] @ W[512,1024], z in {Q,K,V}
    dim3 gq(INNER_ / 64, MROWS / 128, 3);
    gemm_tf32_kernel<D_, INNER_, true><<<gq, 256>>>(
        x, y, Wq, Wk, Wv, Qp, Kp, Vp, pos, nullptr);

    rope_kernel<<<(MROWS * 512) / 256, 256>>>(Qp, Kp);

    attn_kernel<<<B_ * H_ * T_, 128>>>(Qp, Kp, Vp, tmask, Op);

    // Proj: P[4096,512] = O[4096,1024] @ Wo + bo
    dim3 gp(D_ / 64, MROWS / 128, 1);
    gemm_tf32_kernel<INNER_, D_, false><<<gp, 256>>>(
        Op, nullptr, Wo, nullptr, nullptr, Pp, nullptr, nullptr, nullptr, bo);

    gate_kernel<<<MROWS, 128>>>(Pp, gw, gb, out);
}

// round 5
// speedup vs baseline: 3.5357x; 2.7559x over previous
#include <cuda_runtime.h>
#include <math.h>
#include <stdint.h>

// Problem constants
#define B_     2
#define T_     16
#define S_     128
#define D_     512
#define H_     16
#define DH_    64
#define INNER_ 1024
#define NTOK   2048    // T_*S_
#define MROWS  4096    // B_*NTOK

// Scratch (device globals; no allocation allowed in kernel_launch)
__device__ float g_Q[MROWS * INNER_];
__device__ float g_K[MROWS * INNER_];
__device__ float g_V[MROWS * INNER_];
__device__ float g_O[MROWS * INNER_];   // attention output
__device__ float g_P[MROWS * D_];       // output projection result

// ---------------------------------------------------------------------------
// tf32 helpers
// ---------------------------------------------------------------------------
__device__ __forceinline__ uint32_t f2tf32(float f) {
    uint32_t u;
    asm("cvt.rna.tf32.f32 %0, %1;" : "=r"(u) : "f"(f));
    return u;
}

__device__ __forceinline__ void mma_tf32(float* c, const uint32_t* a,
                                         const uint32_t* b) {
    asm volatile(
        "mma.sync.aligned.m16n8k8.row.col.f32.tf32.tf32.f32 "
        "{%0,%1,%2,%3},{%4,%5,%6,%7},{%8,%9},{%0,%1,%2,%3};"
        : "+f"(c[0]), "+f"(c[1]), "+f"(c[2]), "+f"(c[3])
        : "r"(a[0]), "r"(a[1]), "r"(a[2]), "r"(a[3]), "r"(b[0]), "r"(b[1]));
}

// ---------------------------------------------------------------------------
// tf32 tensor-core GEMM. CTA tile 128x64, BK=32, 256 threads (8 warps, 4x2).
// QKV=true: blockIdx.z selects (x,Wq)->Q / (x,Wk)->K / (y,Wv)->V with fused
// pos_emb add on A. QKV=false: single GEMM with fused bias (output proj).
// ---------------------------------------------------------------------------
#define AS_STRIDE 36
#define BS_STRIDE 72

template<int KDIM, int NDIM, bool QKV>
__global__ void __launch_bounds__(256) gemm_tf32_kernel(
    const float* __restrict__ x, const float* __restrict__ y,
    const float* __restrict__ W0, const float* __restrict__ W1,
    const float* __restrict__ W2,
    float* __restrict__ C0, float* __restrict__ C1, float* __restrict__ C2,
    const float* __restrict__ pos, const float* __restrict__ bias)
{
    __shared__ uint32_t As[128 * AS_STRIDE];
    __shared__ uint32_t Bs[32 * BS_STRIDE];

    const float* A;
    const float* W;
    float* C;
    if (QKV) {
        int z = blockIdx.z;
        A = (z == 2) ? y : x;
        W = (z == 0) ? W0 : (z == 1) ? W1 : W2;
        C = (z == 0) ? C0 : (z == 1) ? C1 : C2;
    } else {
        A = x; W = W0; C = C0;
    }

    int tid  = threadIdx.x;
    int lane = tid & 31;
    int wid  = tid >> 5;
    int warpM = wid >> 1;
    int warpN = wid & 1;
    int m0 = blockIdx.y * 128;
    int n0 = blockIdx.x * 64;

    int aIdx[4], aRow[4], aCol[4];
#pragma unroll
    for (int i = 0; i < 4; i++) {
        aIdx[i] = tid + i * 256;
        aRow[i] = aIdx[i] >> 3;
        aCol[i] = (aIdx[i] & 7) * 4;
    }
    int bRow[2], bCol[2];
#pragma unroll
    for (int i = 0; i < 2; i++) {
        int idx = tid + i * 256;
        bRow[i] = idx >> 4;
        bCol[i] = (idx & 15) * 4;
    }

    float acc[2][4][4];
#pragma unroll
    for (int mt = 0; mt < 2; mt++)
#pragma unroll
        for (int nt = 0; nt < 4; nt++)
#pragma unroll
            for (int e = 0; e < 4; e++) acc[mt][nt][e] = 0.f;

    uint32_t aReg[4][4];
    uint32_t bReg[2][4];

#pragma unroll
    for (int i = 0; i < 4; i++) {
        float4 a4 = *(const float4*)(A + (size_t)(m0 + aRow[i]) * KDIM + aCol[i]);
        if (QKV) {
            int t = ((m0 + aRow[i]) & (NTOK - 1)) >> 7;
            float4 p4 = *(const float4*)(pos + t * D_ + aCol[i]);
            a4.x += p4.x; a4.y += p4.y; a4.z += p4.z; a4.w += p4.w;
        }
        aReg[i][0] = f2tf32(a4.x); aReg[i][1] = f2tf32(a4.y);
        aReg[i][2] = f2tf32(a4.z); aReg[i][3] = f2tf32(a4.w);
    }
#pragma unroll
    for (int i = 0; i < 2; i++) {
        float4 b4 = *(const float4*)(W + (size_t)bRow[i] * NDIM + n0 + bCol[i]);
        bReg[i][0] = f2tf32(b4.x); bReg[i][1] = f2tf32(b4.y);
        bReg[i][2] = f2tf32(b4.z); bReg[i][3] = f2tf32(b4.w);
    }

    for (int k0 = 0; k0 < KDIM; k0 += 32) {
        __syncthreads();
#pragma unroll
        for (int i = 0; i < 4; i++)
            *(uint4*)&As[aRow[i] * AS_STRIDE + aCol[i]] =
                make_uint4(aReg[i][0], aReg[i][1], aReg[i][2], aReg[i][3]);
#pragma unroll
        for (int i = 0; i < 2; i++)
            *(uint4*)&Bs[bRow[i] * BS_STRIDE + bCol[i]] =
                make_uint4(bReg[i][0], bReg[i][1], bReg[i][2], bReg[i][3]);
        __syncthreads();

        int kn = k0 + 32;
        if (kn < KDIM) {
#pragma unroll
            for (int i = 0; i < 4; i++) {
                float4 a4 = *(const float4*)(A + (size_t)(m0 + aRow[i]) * KDIM + kn + aCol[i]);
                if (QKV) {
                    int t = ((m0 + aRow[i]) & (NTOK - 1)) >> 7;
                    float4 p4 = *(const float4*)(pos + t * D_ + kn + aCol[i]);
                    a4.x += p4.x; a4.y += p4.y; a4.z += p4.z; a4.w += p4.w;
                }
                aReg[i][0] = f2tf32(a4.x); aReg[i][1] = f2tf32(a4.y);
                aReg[i][2] = f2tf32(a4.z); aReg[i][3] = f2tf32(a4.w);
            }
#pragma unroll
            for (int i = 0; i < 2; i++) {
                float4 b4 = *(const float4*)(W + (size_t)(kn + bRow[i]) * NDIM + n0 + bCol[i]);
                bReg[i][0] = f2tf32(b4.x); bReg[i][1] = f2tf32(b4.y);
                bReg[i][2] = f2tf32(b4.z); bReg[i][3] = f2tf32(b4.w);
            }
        }

#pragma unroll
        for (int ks = 0; ks < 4; ks++) {
            uint32_t af[2][4];
            uint32_t bf[4][2];
#pragma unroll
            for (int mt = 0; mt < 2; mt++) {
                int rb = warpM * 32 + mt * 16 + (lane >> 2);
                int c0 = ks * 8 + (lane & 3);
                af[mt][0] = As[rb * AS_STRIDE + c0];
                af[mt][1] = As[(rb + 8) * AS_STRIDE + c0];
                af[mt][2] = As[rb * AS_STRIDE + c0 + 4];
                af[mt][3] = As[(rb + 8) * AS_STRIDE + c0 + 4];
            }
#pragma unroll
            for (int nt = 0; nt < 4; nt++) {
                int col = warpN * 32 + nt * 8 + (lane >> 2);
                int r = ks * 8 + (lane & 3);
                bf[nt][0] = Bs[r * BS_STRIDE + col];
                bf[nt][1] = Bs[(r + 4) * BS_STRIDE + col];
            }
#pragma unroll
            for (int mt = 0; mt < 2; mt++)
#pragma unroll
                for (int nt = 0; nt < 4; nt++)
                    mma_tf32(acc[mt][nt], af[mt], bf[nt]);
        }
    }

#pragma unroll
    for (int mt = 0; mt < 2; mt++) {
#pragma unroll
        for (int nt = 0; nt < 4; nt++) {
            int row = m0 + warpM * 32 + mt * 16 + (lane >> 2);
            int col = n0 + warpN * 32 + nt * 8 + 2 * (lane & 3);
            float b0 = 0.f, b1 = 0.f;
            if (!QKV) { b0 = bias[col]; b1 = bias[col + 1]; }
            *(float2*)(C + (size_t)row * NDIM + col) =
                make_float2(acc[mt][nt][0] + b0, acc[mt][nt][1] + b1);
            *(float2*)(C + (size_t)(row + 8) * NDIM + col) =
                make_float2(acc[mt][nt][2] + b0, acc[mt][nt][3] + b1);
        }
    }
}

// ---------------------------------------------------------------------------
// RoPE over flattened token index, in-place on Q and K.
// ---------------------------------------------------------------------------
__global__ void __launch_bounds__(256) rope_kernel(float* __restrict__ Q,
                                                   float* __restrict__ Kt)
{
    int gid = blockIdx.x * blockDim.x + threadIdx.x;
    int m  = gid >> 9;
    int r  = gid & 511;
    int h  = r >> 5;
    int dd = r & 31;
    int i  = m & (NTOK - 1);

    float inv = exp2f(-(float)dd * (13.287712379549449f / 32.0f));
    float f = (float)i * inv;
    float c = cosf(f), s = sinf(f);

    size_t base = (size_t)m * INNER_ + h * DH_ + dd;
    float a = Q[base], b2 = Q[base + 32];
    Q[base]      = a * c - b2 * s;
    Q[base + 32] = b2 * c + a * s;
    a = Kt[base]; b2 = Kt[base + 32];
    Kt[base]      = a * c - b2 * s;
    Kt[base + 32] = b2 * c + a * s;
}

// ---------------------------------------------------------------------------
// Flash attention with tf32 mma. Block = (b, h, ti): 128 query rows, 4 warps,
// warp w owns rows 32w..32w+31. Keys processed in 32-wide chunks; masked
// temporal blocks skipped. Online softmax in fp32; P round-trips through
// warp-private smem to become an A-operand for the PV mma.
//
// smem union (uint32): [0, 8704)  Q staging 128 x (stride 68)
//   main phase: K chunk at 0 (32 x 68), V chunk at 2176 (32 x 68),
//               P panes at 4352 (4 warps x 32 x stride 36)
// ---------------------------------------------------------------------------
#define KS_OFF 0
#define VS_OFF 2176
#define PS_OFF 4352
#define QSTR   68
#define PSTR   36

__global__ void __launch_bounds__(128) attn_mma_kernel(
    const float* __restrict__ Q, const float* __restrict__ K,
    const float* __restrict__ V, const int* __restrict__ tmask,
    float* __restrict__ O)
{
    __shared__ uint32_t sm[8960];

    int blk  = blockIdx.x;               // ((b*H + h)*T + ti)
    int ti   = blk % T_;
    int bh   = blk / T_;
    int h    = bh % H_;
    int b    = bh / H_;
    int tid  = threadIdx.x;
    int lane = tid & 31;
    int warp = tid >> 5;

    // ---- stage Q tile (128 x 64) as tf32 ----
    {
        const float* qg = Q + ((size_t)(b * NTOK + ti * S_)) * INNER_ + h * DH_;
#pragma unroll
        for (int i = 0; i < 16; i++) {
            int idx = tid + i * 128;
            int row = idx >> 4, c4 = (idx & 15) * 4;
            float4 v4 = *(const float4*)(qg + (size_t)row * INNER_ + c4);
            *(uint4*)&sm[row * QSTR + c4] =
                make_uint4(f2tf32(v4.x), f2tf32(v4.y), f2tf32(v4.z), f2tf32(v4.w));
        }
    }
    __syncthreads();

    // ---- Q A-fragments (held in registers for the whole kernel) ----
    uint32_t qf[2][8][4];
#pragma unroll
    for (int mt = 0; mt < 2; mt++)
#pragma unroll
        for (int kt = 0; kt < 8; kt++) {
            int r0 = warp * 32 + mt * 16 + (lane >> 2);
            int c  = kt * 8 + (lane & 3);
            qf[mt][kt][0] = sm[r0 * QSTR + c];
            qf[mt][kt][1] = sm[(r0 + 8) * QSTR + c];
            qf[mt][kt][2] = sm[r0 * QSTR + c + 4];
            qf[mt][kt][3] = sm[(r0 + 8) * QSTR + c + 4];
        }

    float of[2][8][4];
#pragma unroll
    for (int mt = 0; mt < 2; mt++)
#pragma unroll
        for (int nt = 0; nt < 8; nt++)
#pragma unroll
            for (int e = 0; e < 4; e++) of[mt][nt][e] = 0.f;
    float mx[2][2]  = {{-1e30f, -1e30f}, {-1e30f, -1e30f}};
    float ell[2][2] = {{0.f, 0.f}, {0.f, 0.f}};

    uint32_t pw = PS_OFF + warp * (32 * PSTR);   // warp-private P pane

    for (int tj = 0; tj < T_; tj++) {
        if (tmask[(b * T_ + ti) * T_ + tj] == 0) continue;
#pragma unroll 1
        for (int ch = 0; ch < 4; ch++) {
            // ---- load K,V chunk (32 keys x 64) as tf32 ----
            const float* kb = K + ((size_t)(b * NTOK + tj * S_ + ch * 32)) * INNER_ + h * DH_;
            const float* vb = V + ((size_t)(b * NTOK + tj * S_ + ch * 32)) * INNER_ + h * DH_;
            __syncthreads();
#pragma unroll
            for (int i = 0; i < 4; i++) {
                int idx = tid + i * 128;
                int row = idx >> 4, c4 = (idx & 15) * 4;
                float4 k4 = *(const float4*)(kb + (size_t)row * INNER_ + c4);
                *(uint4*)&sm[KS_OFF + row * QSTR + c4] =
                    make_uint4(f2tf32(k4.x), f2tf32(k4.y), f2tf32(k4.z), f2tf32(k4.w));
                float4 v4 = *(const float4*)(vb + (size_t)row * INNER_ + c4);
                *(uint4*)&sm[VS_OFF + row * QSTR + c4] =
                    make_uint4(f2tf32(v4.x), f2tf32(v4.y), f2tf32(v4.z), f2tf32(v4.w));
            }
            __syncthreads();

            // ---- S = Q * K^T  (warp: 32 rows x 32 keys) ----
            float sf[2][4][4];
#pragma unroll
            for (int mt = 0; mt < 2; mt++)
#pragma unroll
                for (int nt = 0; nt < 4; nt++)
#pragma unroll
                    for (int e = 0; e < 4; e++) sf[mt][nt][e] = 0.f;

#pragma unroll
            for (int kt = 0; kt < 8; kt++) {
                uint32_t bf[4][2];
#pragma unroll
                for (int nt = 0; nt < 4; nt++) {
                    int n = nt * 8 + (lane >> 2);
                    int c = kt * 8 + (lane & 3);
                    bf[nt][0] = sm[KS_OFF + n * QSTR + c];
                    bf[nt][1] = sm[KS_OFF + n * QSTR + c + 4];
                }
#pragma unroll
                for (int mt = 0; mt < 2; mt++)
#pragma unroll
                    for (int nt = 0; nt < 4; nt++)
                        mma_tf32(sf[mt][nt], qf[mt][kt], bf[nt]);
            }

            // ---- online softmax + write P (tf32) to warp pane ----
#pragma unroll
            for (int mt = 0; mt < 2; mt++) {
#pragma unroll
                for (int hh = 0; hh < 2; hh++) {
                    float cm = -1e30f;
#pragma unroll
                    for (int nt = 0; nt < 4; nt++) {
                        float s0 = sf[mt][nt][2 * hh]     * 0.125f;
                        float s1 = sf[mt][nt][2 * hh + 1] * 0.125f;
                        sf[mt][nt][2 * hh]     = s0;
                        sf[mt][nt][2 * hh + 1] = s1;
                        cm = fmaxf(cm, fmaxf(s0, s1));
                    }
                    cm = fmaxf(cm, __shfl_xor_sync(0xffffffffu, cm, 1));
                    cm = fmaxf(cm, __shfl_xor_sync(0xffffffffu, cm, 2));
                    float nm = fmaxf(mx[mt][hh], cm);
                    float corr = __expf(mx[mt][hh] - nm);
                    mx[mt][hh] = nm;
                    ell[mt][hh] *= corr;
#pragma unroll
                    for (int nt = 0; nt < 8; nt++) {
                        of[mt][nt][2 * hh]     *= corr;
                        of[mt][nt][2 * hh + 1] *= corr;
                    }
                    float rs = 0.f;
                    int rloc = mt * 16 + (lane >> 2) + hh * 8;
#pragma unroll
                    for (int nt = 0; nt < 4; nt++) {
                        float p0 = __expf(sf[mt][nt][2 * hh]     - nm);
                        float p1 = __expf(sf[mt][nt][2 * hh + 1] - nm);
                        rs += p0 + p1;
                        *(uint2*)&sm[pw + rloc * PSTR + nt * 8 + 2 * (lane & 3)] =
                            make_uint2(f2tf32(p0), f2tf32(p1));
                    }
                    rs += __shfl_xor_sync(0xffffffffu, rs, 1);
                    rs += __shfl_xor_sync(0xffffffffu, rs, 2);
                    ell[mt][hh] += rs;
                }
            }
            __syncwarp();

            // ---- O += P * V ----
#pragma unroll
            for (int kt = 0; kt < 4; kt++) {
                uint32_t pf[2][4];
#pragma unroll
                for (int mt = 0; mt < 2; mt++) {
                    int r0 = mt * 16 + (lane >> 2);
                    int c  = kt * 8 + (lane & 3);
                    pf[mt][0] = sm[pw + r0 * PSTR + c];
                    pf[mt][1] = sm[pw + (r0 + 8) * PSTR + c];
                    pf[mt][2] = sm[pw + r0 * PSTR + c + 4];
                    pf[mt][3] = sm[pw + (r0 + 8) * PSTR + c + 4];
                }
                uint32_t vf[8][2];
#pragma unroll
                for (int nt = 0; nt < 8; nt++) {
                    int n = nt * 8 + (lane >> 2);
                    int k = kt * 8 + (lane & 3);
                    vf[nt][0] = sm[VS_OFF + k * QSTR + n];
                    vf[nt][1] = sm[VS_OFF + (k + 4) * QSTR + n];
                }
#pragma unroll
                for (int mt = 0; mt < 2; mt++)
#pragma unroll
                    for (int nt = 0; nt < 8; nt++)
                        mma_tf32(of[mt][nt], pf[mt], vf[nt]);
            }
            __syncwarp();
        }
    }

    // ---- normalize and write O ----
#pragma unroll
    for (int mt = 0; mt < 2; mt++) {
#pragma unroll
        for (int hh = 0; hh < 2; hh++) {
            float inv = (ell[mt][hh] > 0.f) ? (1.f / ell[mt][hh]) : 0.f;
            int row = b * NTOK + ti * S_ + warp * 32 + mt * 16 + (lane >> 2) + hh * 8;
#pragma unroll
            for (int nt = 0; nt < 8; nt++) {
                int col = h * DH_ + nt * 8 + 2 * (lane & 3);
                *(float2*)(O + (size_t)row * INNER_ + col) =
                    make_float2(of[mt][nt][2 * hh] * inv, of[mt][nt][2 * hh + 1] * inv);
            }
        }
    }
}

// ---------------------------------------------------------------------------
// Gate: per row of P[4096,512]: g = sigmoid(dot(row, gate_w) + gate_b).
// ---------------------------------------------------------------------------
__global__ void __launch_bounds__(128) gate_kernel(
    const float* __restrict__ P, const float* __restrict__ gw,
    const float* __restrict__ gb, float* __restrict__ out)
{
    int m = blockIdx.x;
    int tid = threadIdx.x;
    const float* row = P + (size_t)m * D_;

    float v[4];
    float part = 0.f;
#pragma unroll
    for (int r = 0; r < 4; r++) {
        int j = tid + r * 128;
        v[r] = row[j];
        part += v[r] * gw[j];
    }
#pragma unroll
    for (int off = 16; off; off >>= 1)
        part += __shfl_xor_sync(0xffffffffu, part, off);

    __shared__ float red[4];
    if ((tid & 31) == 0) red[tid >> 5] = part;
    __syncthreads();
    float tot = red[0] + red[1] + red[2] + red[3] + gb[0];
    float gate = 1.f / (1.f + __expf(-tot));

    float* orow = out + (size_t)m * D_;
#pragma unroll
    for (int r = 0; r < 4; r++) {
        int j = tid + r * 128;
        orow[j] = v[r] * gate;
    }
}

// ---------------------------------------------------------------------------
extern "C" void kernel_launch(void* const* d_in, const int* in_sizes, int n_in,
                              void* d_out, int out_size)
{
    (void)in_sizes; (void)n_in; (void)out_size;
    const float* x     = (const float*)d_in[0];
    const float* y     = (const float*)d_in[1];
    const int*   tmask = (const int*)  d_in[2];
    const float* Wq    = (const float*)d_in[3];
    const float* Wk    = (const float*)d_in[4];
    const float* Wv    = (const float*)d_in[5];
    const float* Wo    = (const float*)d_in[6];
    const float* bo    = (const float*)d_in[7];
    const float* pos   = (const float*)d_in[8];
    const float* gw    = (const float*)d_in[9];
    const float* gb    = (const float*)d_in[10];
    float* out = (float*)d_out;

    float *Qp, *Kp, *Vp, *Op, *Pp;
    cudaGetSymbolAddress((void**)&Qp, g_Q);
    cudaGetSymbolAddress((void**)&Kp, g_K);
    cudaGetSymbolAddress((void**)&Vp, g_V);
    cudaGetSymbolAddress((void**)&Op, g_O);
    cudaGetSymbolAddress((void**)&Pp, g_P);

    // QKV: C[4096,1024] = (A+pos)[4096,512] @ W[512,1024], z in {Q,K,V}
    dim3 gq(INNER_ / 64, MROWS / 128, 3);
    gemm_tf32_kernel<D_, INNER_, true><<<gq, 256>>>(
        x, y, Wq, Wk, Wv, Qp, Kp, Vp, pos, nullptr);

    rope_kernel<<<(MROWS * 512) / 256, 256>>>(Qp, Kp);

    attn_mma_kernel<<<B_ * H_ * T_, 128>>>(Qp, Kp, Vp, tmask, Op);

    // Proj: P[4096,512] = O[4096,1024] @ Wo + bo
    dim3 gp(D_ / 64, MROWS / 128, 1);
    gemm_tf32_kernel<INNER_, D_, false><<<gp, 256>>>(
        Op, nullptr, Wo, nullptr, nullptr, Pp, nullptr, nullptr, nullptr, bo);

    gate_kernel<<<MROWS, 128>>>(Pp, gw, gb, out);
}

// round 6
// speedup vs baseline: 3.8360x; 1.0849x over previous
#include <cuda_runtime.h>
#include <math.h>
#include <stdint.h>

// Problem constants
#define B_     2
#define T_     16
#define S_     128
#define D_     512
#define H_     16
#define DH_    64
#define INNER_ 1024
#define NTOK   2048    // T_*S_
#define MROWS  4096    // B_*NTOK
#define HALF_XY 2097152   // MROWS*D_ elements per x/y plane
#define WSEG    524288    // 512*1024 elements per weight matrix

// Scratch (device globals)
__device__ float g_Q[MROWS * INNER_];
__device__ float g_K[MROWS * INNER_];
__device__ float g_V[MROWS * INNER_];
__device__ float g_O[MROWS * INNER_];   // holds xp|yp during qkv, then attn out
__device__ float g_P[MROWS * D_];       // output projection result
__device__ float g_W[4 * WSEG];         // tf32-rounded Wq|Wk|Wv|Wo

// ---------------------------------------------------------------------------
// helpers
// ---------------------------------------------------------------------------
__device__ __forceinline__ uint32_t f2tf32(float f) {
    uint32_t u;
    asm("cvt.rna.tf32.f32 %0, %1;" : "=r"(u) : "f"(f));
    return u;
}

__device__ __forceinline__ void mma_tf32(float* c, const uint32_t* a,
                                         const uint32_t* b) {
    asm volatile(
        "mma.sync.aligned.m16n8k8.row.col.f32.tf32.tf32.f32 "
        "{%0,%1,%2,%3},{%4,%5,%6,%7},{%8,%9},{%0,%1,%2,%3};"
        : "+f"(c[0]), "+f"(c[1]), "+f"(c[2]), "+f"(c[3])
        : "r"(a[0]), "r"(a[1]), "r"(a[2]), "r"(a[3]), "r"(b[0]), "r"(b[1]));
}

__device__ __forceinline__ void cp16(uint32_t dst, const void* src) {
    asm volatile("cp.async.cg.shared.global [%0], [%1], 16;" :: "r"(dst), "l"(src));
}
__device__ __forceinline__ void cp_commit() {
    asm volatile("cp.async.commit_group;");
}
template<int N> __device__ __forceinline__ void cp_wait() {
    asm volatile("cp.async.wait_group %0;" :: "n"(N));
}

// ---------------------------------------------------------------------------
// prep: xp = tf32(x + pos), yp = tf32(y + pos)  (into g_O halves)
// ---------------------------------------------------------------------------
__global__ void __launch_bounds__(256) prep_xy_kernel(
    const float* __restrict__ x, const float* __restrict__ y,
    const float* __restrict__ pos, float* __restrict__ xp,
    float* __restrict__ yp)
{
    int i = blockIdx.x * blockDim.x + threadIdx.x;   // [0, HALF_XY)
    int m = i >> 9;
    int d = i & 511;
    int t = (m & (NTOK - 1)) >> 7;
    float p = pos[t * D_ + d];
    xp[i] = __uint_as_float(f2tf32(x[i] + p));
    yp[i] = __uint_as_float(f2tf32(y[i] + p));
}

// prep: g_W = tf32([Wq|Wk|Wv|Wo])
__global__ void __launch_bounds__(256) prep_w_kernel(
    const float* __restrict__ Wq, const float* __restrict__ Wk,
    const float* __restrict__ Wv, const float* __restrict__ Wo,
    float* __restrict__ Wc)
{
    int i = blockIdx.x * blockDim.x + threadIdx.x;   // [0, 4*WSEG)
    int seg = i >> 19;
    int off = i & (WSEG - 1);
    const float* src = (seg == 0) ? Wq : (seg == 1) ? Wk : (seg == 2) ? Wv : Wo;
    Wc[i] = __uint_as_float(f2tf32(src[off]));
}

// ---------------------------------------------------------------------------
// GEMM v2: CTA 128x128, 4 warps of 64x64, BK=16, cp.async double buffer.
// Inputs are pre-rounded tf32 (raw bits valid as mma operands).
// MODE 0: qkv (z selects xp/yp and Wq/Wk/Wv; V output tf32-rounded)
// MODE 1: proj (bias add, fp32 output)
// ---------------------------------------------------------------------------
#define ASTR 20
#define BSTR 136

template<int KDIM, int NDIM, int MODE>
__global__ void __launch_bounds__(128) gemm2_kernel(
    const float* __restrict__ Abase, const float* __restrict__ Wbase,
    float* __restrict__ C0, float* __restrict__ C1, float* __restrict__ C2,
    const float* __restrict__ bias)
{
    __shared__ float smA[2][128 * ASTR];
    __shared__ float smB[2][16 * BSTR];

    const float* A;
    const float* W;
    float* C;
    int z = 0;
    if (MODE == 0) {
        z = blockIdx.z;
        A = Abase + ((z == 2) ? HALF_XY : 0);
        W = Wbase + z * WSEG;
        C = (z == 0) ? C0 : (z == 1) ? C1 : C2;
    } else {
        A = Abase; W = Wbase; C = C0;
    }

    int tid   = threadIdx.x;
    int lane  = tid & 31;
    int warp  = tid >> 5;
    int warpM = warp >> 1;     // 0..1
    int warpN = warp & 1;      // 0..1
    int m0 = blockIdx.y * 128;
    int n0 = blockIdx.x * 128;

    uint32_t aSm[2], bSm[2];
    aSm[0] = (uint32_t)__cvta_generic_to_shared(&smA[0][0]);
    aSm[1] = (uint32_t)__cvta_generic_to_shared(&smA[1][0]);
    bSm[0] = (uint32_t)__cvta_generic_to_shared(&smB[0][0]);
    bSm[1] = (uint32_t)__cvta_generic_to_shared(&smB[1][0]);

    const int NS = KDIM / 16;

    // slab loader: A 128x16 (512 chunks), B 16x128 (512 chunks); 4 each/thread
    auto load_slab = [&](int s, int buf) {
#pragma unroll
        for (int i = 0; i < 4; i++) {
            int q = tid + i * 128;
            int ar = q >> 2, ac = (q & 3) * 4;
            cp16(aSm[buf] + (uint32_t)(ar * ASTR + ac) * 4,
                 A + (size_t)(m0 + ar) * KDIM + s * 16 + ac);
            int br = q >> 5, bc = (q & 31) * 4;
            cp16(bSm[buf] + (uint32_t)(br * BSTR + bc) * 4,
                 W + (size_t)(s * 16 + br) * NDIM + n0 + bc);
        }
        cp_commit();
    };

    float acc[4][8][4];
#pragma unroll
    for (int mt = 0; mt < 4; mt++)
#pragma unroll
        for (int nt = 0; nt < 8; nt++)
#pragma unroll
            for (int e = 0; e < 4; e++) acc[mt][nt][e] = 0.f;

    load_slab(0, 0);

    for (int s = 0; s < NS; s++) {
        int buf = s & 1;
        if (s + 1 < NS) {
            load_slab(s + 1, buf ^ 1);
            cp_wait<1>();
        } else {
            cp_wait<0>();
        }
        __syncthreads();

        const uint32_t* uA = (const uint32_t*)smA[buf];
        const uint32_t* uB = (const uint32_t*)smB[buf];
#pragma unroll
        for (int ks = 0; ks < 2; ks++) {
            uint32_t af[4][4];
#pragma unroll
            for (int mt = 0; mt < 4; mt++) {
                int r0 = warpM * 64 + mt * 16 + (lane >> 2);
                int c  = ks * 8 + (lane & 3);
                af[mt][0] = uA[r0 * ASTR + c];
                af[mt][1] = uA[(r0 + 8) * ASTR + c];
                af[mt][2] = uA[r0 * ASTR + c + 4];
                af[mt][3] = uA[(r0 + 8) * ASTR + c + 4];
            }
            uint32_t bf[8][2];
#pragma unroll
            for (int nt = 0; nt < 8; nt++) {
                int n = warpN * 64 + nt * 8 + (lane >> 2);
                int k = ks * 8 + (lane & 3);
                bf[nt][0] = uB[k * BSTR + n];
                bf[nt][1] = uB[(k + 4) * BSTR + n];
            }
#pragma unroll
            for (int mt = 0; mt < 4; mt++)
#pragma unroll
                for (int nt = 0; nt < 8; nt++)
                    mma_tf32(acc[mt][nt], af[mt], bf[nt]);
        }
        __syncthreads();
    }

    // epilogue
#pragma unroll
    for (int mt = 0; mt < 4; mt++) {
#pragma unroll
        for (int nt = 0; nt < 8; nt++) {
            int row = m0 + warpM * 64 + mt * 16 + (lane >> 2);
            int col = n0 + warpN * 64 + nt * 8 + 2 * (lane & 3);
            if (MODE == 1) {
                float b0 = bias[col], b1 = bias[col + 1];
                *(float2*)(C + (size_t)row * NDIM + col) =
                    make_float2(acc[mt][nt][0] + b0, acc[mt][nt][1] + b1);
                *(float2*)(C + (size_t)(row + 8) * NDIM + col) =
                    make_float2(acc[mt][nt][2] + b0, acc[mt][nt][3] + b1);
            } else if (z == 2) {
                // V: tf32-round for the attention mma
                *(uint2*)(C + (size_t)row * NDIM + col) =
                    make_uint2(f2tf32(acc[mt][nt][0]), f2tf32(acc[mt][nt][1]));
                *(uint2*)(C + (size_t)(row + 8) * NDIM + col) =
                    make_uint2(f2tf32(acc[mt][nt][2]), f2tf32(acc[mt][nt][3]));
            } else {
                // Q/K: fp32 (rope kernel rounds after rotating)
                *(float2*)(C + (size_t)row * NDIM + col) =
                    make_float2(acc[mt][nt][0], acc[mt][nt][1]);
                *(float2*)(C + (size_t)(row + 8) * NDIM + col) =
                    make_float2(acc[mt][nt][2], acc[mt][nt][3]);
            }
        }
    }
}

// ---------------------------------------------------------------------------
// RoPE in-place on Q and K; writes tf32-rounded values (attn consumes raw).
// ---------------------------------------------------------------------------
__global__ void __launch_bounds__(256) rope_kernel(float* __restrict__ Q,
                                                   float* __restrict__ Kt)
{
    int gid = blockIdx.x * blockDim.x + threadIdx.x;
    int m  = gid >> 9;
    int r  = gid & 511;
    int h  = r >> 5;
    int dd = r & 31;
    int i  = m & (NTOK - 1);

    float inv = exp2f(-(float)dd * (13.287712379549449f / 32.0f));
    float f = (float)i * inv;
    float c = cosf(f), s = sinf(f);

    size_t base = (size_t)m * INNER_ + h * DH_ + dd;
    float a = Q[base], b2 = Q[base + 32];
    Q[base]      = __uint_as_float(f2tf32(a * c - b2 * s));
    Q[base + 32] = __uint_as_float(f2tf32(b2 * c + a * s));
    a = Kt[base]; b2 = Kt[base + 32];
    Kt[base]      = __uint_as_float(f2tf32(a * c - b2 * s));
    Kt[base + 32] = __uint_as_float(f2tf32(b2 * c + a * s));
}

// ---------------------------------------------------------------------------
// Flash attention, tf32 mma. Inputs Q/K/V already tf32-rounded bits.
// Output O stored tf32-rounded (proj consumes raw).
// ---------------------------------------------------------------------------
#define KS_OFF 0
#define VS_OFF 2176
#define PS_OFF 4352
#define QSTR   68
#define PSTR   36

__global__ void __launch_bounds__(128) attn_mma_kernel(
    const float* __restrict__ Q, const float* __restrict__ K,
    const float* __restrict__ V, const int* __restrict__ tmask,
    float* __restrict__ O)
{
    __shared__ uint32_t sm[8960];

    int blk  = blockIdx.x;
    int ti   = blk % T_;
    int bh   = blk / T_;
    int h    = bh % H_;
    int b    = bh / H_;
    int tid  = threadIdx.x;
    int lane = tid & 31;
    int warp = tid >> 5;

    // stage Q (raw bits, already tf32)
    {
        const float* qg = Q + ((size_t)(b * NTOK + ti * S_)) * INNER_ + h * DH_;
#pragma unroll
        for (int i = 0; i < 16; i++) {
            int idx = tid + i * 128;
            int row = idx >> 4, c4 = (idx & 15) * 4;
            float4 v4 = *(const float4*)(qg + (size_t)row * INNER_ + c4);
            *(uint4*)&sm[row * QSTR + c4] =
                make_uint4(__float_as_uint(v4.x), __float_as_uint(v4.y),
                           __float_as_uint(v4.z), __float_as_uint(v4.w));
        }
    }
    __syncthreads();

    uint32_t qf[2][8][4];
#pragma unroll
    for (int mt = 0; mt < 2; mt++)
#pragma unroll
        for (int kt = 0; kt < 8; kt++) {
            int r0 = warp * 32 + mt * 16 + (lane >> 2);
            int c  = kt * 8 + (lane & 3);
            qf[mt][kt][0] = sm[r0 * QSTR + c];
            qf[mt][kt][1] = sm[(r0 + 8) * QSTR + c];
            qf[mt][kt][2] = sm[r0 * QSTR + c + 4];
            qf[mt][kt][3] = sm[(r0 + 8) * QSTR + c + 4];
        }

    float of[2][8][4];
#pragma unroll
    for (int mt = 0; mt < 2; mt++)
#pragma unroll
        for (int nt = 0; nt < 8; nt++)
#pragma unroll
            for (int e = 0; e < 4; e++) of[mt][nt][e] = 0.f;
    float mx[2][2]  = {{-1e30f, -1e30f}, {-1e30f, -1e30f}};
    float ell[2][2] = {{0.f, 0.f}, {0.f, 0.f}};

    uint32_t pw = PS_OFF + warp * (32 * PSTR);

    for (int tj = 0; tj < T_; tj++) {
        if (tmask[(b * T_ + ti) * T_ + tj] == 0) continue;
#pragma unroll 1
        for (int ch = 0; ch < 4; ch++) {
            const float* kb = K + ((size_t)(b * NTOK + tj * S_ + ch * 32)) * INNER_ + h * DH_;
            const float* vb = V + ((size_t)(b * NTOK + tj * S_ + ch * 32)) * INNER_ + h * DH_;
            __syncthreads();
#pragma unroll
            for (int i = 0; i < 4; i++) {
                int idx = tid + i * 128;
                int row = idx >> 4, c4 = (idx & 15) * 4;
                float4 k4 = *(const float4*)(kb + (size_t)row * INNER_ + c4);
                *(uint4*)&sm[KS_OFF + row * QSTR + c4] =
                    make_uint4(__float_as_uint(k4.x), __float_as_uint(k4.y),
                               __float_as_uint(k4.z), __float_as_uint(k4.w));
                float4 v4 = *(const float4*)(vb + (size_t)row * INNER_ + c4);
                *(uint4*)&sm[VS_OFF + row * QSTR + c4] =
                    make_uint4(__float_as_uint(v4.x), __float_as_uint(v4.y),
                               __float_as_uint(v4.z), __float_as_uint(v4.w));
            }
            __syncthreads();

            float sf[2][4][4];
#pragma unroll
            for (int mt = 0; mt < 2; mt++)
#pragma unroll
                for (int nt = 0; nt < 4; nt++)
#pragma unroll
                    for (int e = 0; e < 4; e++) sf[mt][nt][e] = 0.f;

#pragma unroll
            for (int kt = 0; kt < 8; kt++) {
                uint32_t bfr[4][2];
#pragma unroll
                for (int nt = 0; nt < 4; nt++) {
                    int n = nt * 8 + (lane >> 2);
                    int c = kt * 8 + (lane & 3);
                    bfr[nt][0] = sm[KS_OFF + n * QSTR + c];
                    bfr[nt][1] = sm[KS_OFF + n * QSTR + c + 4];
                }
#pragma unroll
                for (int mt = 0; mt < 2; mt++)
#pragma unroll
                    for (int nt = 0; nt < 4; nt++)
                        mma_tf32(sf[mt][nt], qf[mt][kt], bfr[nt]);
            }

#pragma unroll
            for (int mt = 0; mt < 2; mt++) {
#pragma unroll
                for (int hh = 0; hh < 2; hh++) {
                    float cm = -1e30f;
#pragma unroll
                    for (int nt = 0; nt < 4; nt++) {
                        float s0 = sf[mt][nt][2 * hh]     * 0.125f;
                        float s1 = sf[mt][nt][2 * hh + 1] * 0.125f;
                        sf[mt][nt][2 * hh]     = s0;
                        sf[mt][nt][2 * hh + 1] = s1;
                        cm = fmaxf(cm, fmaxf(s0, s1));
                    }
                    cm = fmaxf(cm, __shfl_xor_sync(0xffffffffu, cm, 1));
                    cm = fmaxf(cm, __shfl_xor_sync(0xffffffffu, cm, 2));
                    float nm = fmaxf(mx[mt][hh], cm);
                    float corr = __expf(mx[mt][hh] - nm);
                    mx[mt][hh] = nm;
                    ell[mt][hh] *= corr;
#pragma unroll
                    for (int nt = 0; nt < 8; nt++) {
                        of[mt][nt][2 * hh]     *= corr;
                        of[mt][nt][2 * hh + 1] *= corr;
                    }
                    float rs = 0.f;
                    int rloc = mt * 16 + (lane >> 2) + hh * 8;
#pragma unroll
                    for (int nt = 0; nt < 4; nt++) {
                        float p0 = __expf(sf[mt][nt][2 * hh]     - nm);
                        float p1 = __expf(sf[mt][nt][2 * hh + 1] - nm);
                        rs += p0 + p1;
                        *(uint2*)&sm[pw + rloc * PSTR + nt * 8 + 2 * (lane & 3)] =
                            make_uint2(f2tf32(p0), f2tf32(p1));
                    }
                    rs += __shfl_xor_sync(0xffffffffu, rs, 1);
                    rs += __shfl_xor_sync(0xffffffffu, rs, 2);
                    ell[mt][hh] += rs;
                }
            }
            __syncwarp();

#pragma unroll
            for (int kt = 0; kt < 4; kt++) {
                uint32_t pf[2][4];
#pragma unroll
                for (int mt = 0; mt < 2; mt++) {
                    int r0 = mt * 16 + (lane >> 2);
                    int c  = kt * 8 + (lane & 3);
                    pf[mt][0] = sm[pw + r0 * PSTR + c];
                    pf[mt][1] = sm[pw + (r0 + 8) * PSTR + c];
                    pf[mt][2] = sm[pw + r0 * PSTR + c + 4];
                    pf[mt][3] = sm[pw + (r0 + 8) * PSTR + c + 4];
                }
                uint32_t vf[8][2];
#pragma unroll
                for (int nt = 0; nt < 8; nt++) {
                    int n = nt * 8 + (lane >> 2);
                    int k = kt * 8 + (lane & 3);
                    vf[nt][0] = sm[VS_OFF + k * QSTR + n];
                    vf[nt][1] = sm[VS_OFF + (k + 4) * QSTR + n];
                }
#pragma unroll
                for (int mt = 0; mt < 2; mt++)
#pragma unroll
                    for (int nt = 0; nt < 8; nt++)
                        mma_tf32(of[mt][nt], pf[mt], vf[nt]);
            }
            __syncwarp();
        }
    }

    // normalize + tf32-round + write (proj consumes raw bits)
#pragma unroll
    for (int mt = 0; mt < 2; mt++) {
#pragma unroll
        for (int hh = 0; hh < 2; hh++) {
            float inv = (ell[mt][hh] > 0.f) ? (1.f / ell[mt][hh]) : 0.f;
            int row = b * NTOK + ti * S_ + warp * 32 + mt * 16 + (lane >> 2) + hh * 8;
#pragma unroll
            for (int nt = 0; nt < 8; nt++) {
                int col = h * DH_ + nt * 8 + 2 * (lane & 3);
                *(uint2*)(O + (size_t)row * INNER_ + col) =
                    make_uint2(f2tf32(of[mt][nt][2 * hh] * inv),
                               f2tf32(of[mt][nt][2 * hh + 1] * inv));
            }
        }
    }
}

// ---------------------------------------------------------------------------
// Gate
// ---------------------------------------------------------------------------
__global__ void __launch_bounds__(128) gate_kernel(
    const float* __restrict__ P, const float* __restrict__ gw,
    const float* __restrict__ gb, float* __restrict__ out)
{
    int m = blockIdx.x;
    int tid = threadIdx.x;
    const float* row = P + (size_t)m * D_;

    float v[4];
    float part = 0.f;
#pragma unroll
    for (int r = 0; r < 4; r++) {
        int j = tid + r * 128;
        v[r] = row[j];
        part += v[r] * gw[j];
    }
#pragma unroll
    for (int off = 16; off; off >>= 1)
        part += __shfl_xor_sync(0xffffffffu, part, off);

    __shared__ float red[4];
    if ((tid & 31) == 0) red[tid >> 5] = part;
    __syncthreads();
    float tot = red[0] + red[1] + red[2] + red[3] + gb[0];
    float gate = 1.f / (1.f + __expf(-tot));

    float* orow = out + (size_t)m * D_;
#pragma unroll
    for (int r = 0; r < 4; r++) {
        int j = tid + r * 128;
        orow[j] = v[r] * gate;
    }
}

// ---------------------------------------------------------------------------
extern "C" void kernel_launch(void* const* d_in, const int* in_sizes, int n_in,
                              void* d_out, int out_size)
{
    (void)in_sizes; (void)n_in; (void)out_size;
    const float* x     = (const float*)d_in[0];
    const float* y     = (const float*)d_in[1];
    const int*   tmask = (const int*)  d_in[2];
    const float* Wq    = (const float*)d_in[3];
    const float* Wk    = (const float*)d_in[4];
    const float* Wv    = (const float*)d_in[5];
    const float* Wo    = (const float*)d_in[6];
    const float* bo    = (const float*)d_in[7];
    const float* pos   = (const float*)d_in[8];
    const float* gw    = (const float*)d_in[9];
    const float* gb    = (const float*)d_in[10];
    float* out = (float*)d_out;

    float *Qp, *Kp, *Vp, *Op, *Pp, *Wc;
    cudaGetSymbolAddress((void**)&Qp, g_Q);
    cudaGetSymbolAddress((void**)&Kp, g_K);
    cudaGetSymbolAddress((void**)&Vp, g_V);
    cudaGetSymbolAddress((void**)&Op, g_O);
    cudaGetSymbolAddress((void**)&Pp, g_P);
    cudaGetSymbolAddress((void**)&Wc, g_W);

    // prep: xp/yp into g_O halves, weights into g_W (all tf32-rounded)
    prep_xy_kernel<<<HALF_XY / 256, 256>>>(x, y, pos, Op, Op + HALF_XY);
    prep_w_kernel<<<(4 * WSEG) / 256, 256>>>(Wq, Wk, Wv, Wo, Wc);

    // QKV: [4096,1024] = xp/yp @ Wq/Wk/Wv
    dim3 gq(INNER_ / 128, MROWS / 128, 3);     // 8 x 32 x 3
    gemm2_kernel<D_, INNER_, 0><<<gq, 128>>>(Op, Wc, Qp, Kp, Vp, nullptr);

    rope_kernel<<<(MROWS * 512) / 256, 256>>>(Qp, Kp);

    attn_mma_kernel<<<B_ * H_ * T_, 128>>>(Qp, Kp, Vp, tmask, Op);

    // Proj: [4096,512] = O @ Wo + bo
    dim3 gp(D_ / 128, MROWS / 128, 1);         // 4 x 32
    gemm2_kernel<INNER_, D_, 1><<<gp, 128>>>(Op, Wc + 3 * WSEG, Pp, nullptr,
                                             nullptr, bo);

    gate_kernel<<<MROWS, 128>>>(Pp, gw, gb, out);
}

// round 8
// speedup vs baseline: 4.2452x; 1.1067x over previous
#include <cuda_runtime.h>
#include <math.h>
#include <stdint.h>

// Problem constants
#define B_     2
#define T_     16
#define S_     128
#define D_     512
#define H_     16
#define DH_    64
#define INNER_ 1024
#define NTOK   2048    // T_*S_
#define MROWS  4096    // B_*NTOK
#define HALF_XY 2097152   // MROWS*D_ elements per x/y plane
#define WSEG    524288    // 512*1024 elements per weight matrix

// Scratch (device globals)
__device__ float g_Q[MROWS * INNER_];
__device__ float g_K[MROWS * INNER_];
__device__ float g_V[MROWS * INNER_];
__device__ float g_O[MROWS * INNER_];   // xp|yp during qkv, then attn out
__device__ float g_P[MROWS * D_];       // output projection result
__device__ float g_W[4 * WSEG];         // tf32-rounded Wq|Wk|Wv|Wo

// ---------------------------------------------------------------------------
// helpers
// ---------------------------------------------------------------------------
__device__ __forceinline__ uint32_t f2tf32(float f) {
    uint32_t u;
    asm("cvt.rna.tf32.f32 %0, %1;" : "=r"(u) : "f"(f));
    return u;
}

__device__ __forceinline__ void mma_tf32(float* c, const uint32_t* a,
                                         const uint32_t* b) {
    asm volatile(
        "mma.sync.aligned.m16n8k8.row.col.f32.tf32.tf32.f32 "
        "{%0,%1,%2,%3},{%4,%5,%6,%7},{%8,%9},{%0,%1,%2,%3};"
        : "+f"(c[0]), "+f"(c[1]), "+f"(c[2]), "+f"(c[3])
        : "r"(a[0]), "r"(a[1]), "r"(a[2]), "r"(a[3]), "r"(b[0]), "r"(b[1]));
}

__device__ __forceinline__ void cp16(uint32_t dst, const void* src) {
    asm volatile("cp.async.cg.shared.global [%0], [%1], 16;" :: "r"(dst), "l"(src));
}
__device__ __forceinline__ void cp_commit() {
    asm volatile("cp.async.commit_group;");
}
template<int N> __device__ __forceinline__ void cp_wait() {
    asm volatile("cp.async.wait_group %0;" :: "n"(N));
}

// ---------------------------------------------------------------------------
// prep: xp = tf32(x + pos), yp = tf32(y + pos); weights -> tf32
// ---------------------------------------------------------------------------
__global__ void __launch_bounds__(256) prep_xy_kernel(
    const float* __restrict__ x, const float* __restrict__ y,
    const float* __restrict__ pos, float* __restrict__ xp,
    float* __restrict__ yp)
{
    int i = blockIdx.x * blockDim.x + threadIdx.x;
    int m = i >> 9;
    int d = i & 511;
    int t = (m & (NTOK - 1)) >> 7;
    float p = pos[t * D_ + d];
    xp[i] = __uint_as_float(f2tf32(x[i] + p));
    yp[i] = __uint_as_float(f2tf32(y[i] + p));
}

__global__ void __launch_bounds__(256) prep_w_kernel(
    const float* __restrict__ Wq, const float* __restrict__ Wk,
    const float* __restrict__ Wv, const float* __restrict__ Wo,
    float* __restrict__ Wc)
{
    int i = blockIdx.x * blockDim.x + threadIdx.x;
    int seg = i >> 19;
    int off = i & (WSEG - 1);
    const float* src = (seg == 0) ? Wq : (seg == 1) ? Wk : (seg == 2) ? Wv : Wo;
    Wc[i] = __uint_as_float(f2tf32(src[off]));
}

// ---------------------------------------------------------------------------
// GEMM v3: CTA 128x128, 4 warps of 64x64, BK=32, 2-stage cp.async,
// dynamic smem. MODE 0: qkv (z selects input/weight/output; V tf32-rounded).
// MODE 1: proj (bias, fp32 out).
// smem words: A0@0 (128*36), A1@4608, B0@9216 (32*136), B1@13568; tot 17920.
// ---------------------------------------------------------------------------
#define G_ASTR 36
#define G_BSTR 136
#define G_A0   0
#define G_A1   4608
#define G_B0   9216
#define G_B1   13568
#define G_SMEM_BYTES (17920 * 4)

template<int KDIM, int NDIM, int MODE>
__global__ void __launch_bounds__(128, 2) gemm3_kernel(
    const float* __restrict__ Abase, const float* __restrict__ Wbase,
    float* __restrict__ C0, float* __restrict__ C1, float* __restrict__ C2,
    const float* __restrict__ bias)
{
    extern __shared__ uint32_t dsm[];

    const float* A;
    const float* W;
    float* C;
    int z = 0;
    if (MODE == 0) {
        z = blockIdx.z;
        A = Abase + ((z == 2) ? HALF_XY : 0);
        W = Wbase + z * WSEG;
        C = (z == 0) ? C0 : (z == 1) ? C1 : C2;
    } else {
        A = Abase; W = Wbase; C = C0;
    }

    int tid   = threadIdx.x;
    int lane  = tid & 31;
    int warp  = tid >> 5;
    int warpM = warp >> 1;
    int warpN = warp & 1;
    int m0 = blockIdx.y * 128;
    int n0 = blockIdx.x * 128;

    uint32_t smBase = (uint32_t)__cvta_generic_to_shared(dsm);
    uint32_t aOff[2] = {smBase + G_A0 * 4, smBase + G_A1 * 4};
    uint32_t bOff[2] = {smBase + G_B0 * 4, smBase + G_B1 * 4};

    const int NS = KDIM / 32;

    auto load_slab = [&](int s, int buf) {
#pragma unroll
        for (int i = 0; i < 8; i++) {
            int q = tid + i * 128;
            int ar = q >> 3, ac = (q & 7) * 4;
            cp16(aOff[buf] + (uint32_t)(ar * G_ASTR + ac) * 4,
                 A + (size_t)(m0 + ar) * KDIM + s * 32 + ac);
            int br = q >> 5, bc = (q & 31) * 4;
            cp16(bOff[buf] + (uint32_t)(br * G_BSTR + bc) * 4,
                 W + (size_t)(s * 32 + br) * NDIM + n0 + bc);
        }
        cp_commit();
    };

    float acc[4][8][4];
#pragma unroll
    for (int mt = 0; mt < 4; mt++)
#pragma unroll
        for (int nt = 0; nt < 8; nt++)
#pragma unroll
            for (int e = 0; e < 4; e++) acc[mt][nt][e] = 0.f;

    load_slab(0, 0);

    for (int s = 0; s < NS; s++) {
        int buf = s & 1;
        if (s + 1 < NS) {
            load_slab(s + 1, buf ^ 1);
            cp_wait<1>();
        } else {
            cp_wait<0>();
        }
        __syncthreads();

        const uint32_t* uA = dsm + (buf ? G_A1 : G_A0);
        const uint32_t* uB = dsm + (buf ? G_B1 : G_B0);
#pragma unroll
        for (int ks = 0; ks < 4; ks++) {
            uint32_t af[4][4];
#pragma unroll
            for (int mt = 0; mt < 4; mt++) {
                int r0 = warpM * 64 + mt * 16 + (lane >> 2);
                int c  = ks * 8 + (lane & 3);
                af[mt][0] = uA[r0 * G_ASTR + c];
                af[mt][1] = uA[(r0 + 8) * G_ASTR + c];
                af[mt][2] = uA[r0 * G_ASTR + c + 4];
                af[mt][3] = uA[(r0 + 8) * G_ASTR + c + 4];
            }
            uint32_t bf[8][2];
#pragma unroll
            for (int nt = 0; nt < 8; nt++) {
                int n = warpN * 64 + nt * 8 + (lane >> 2);
                int k = ks * 8 + (lane & 3);
                bf[nt][0] = uB[k * G_BSTR + n];
                bf[nt][1] = uB[(k + 4) * G_BSTR + n];
            }
#pragma unroll
            for (int mt = 0; mt < 4; mt++)
#pragma unroll
                for (int nt = 0; nt < 8; nt++)
                    mma_tf32(acc[mt][nt], af[mt], bf[nt]);
        }
        __syncthreads();
    }

#pragma unroll
    for (int mt = 0; mt < 4; mt++) {
#pragma unroll
        for (int nt = 0; nt < 8; nt++) {
            int row = m0 + warpM * 64 + mt * 16 + (lane >> 2);
            int col = n0 + warpN * 64 + nt * 8 + 2 * (lane & 3);
            if (MODE == 1) {
                float b0 = bias[col], b1 = bias[col + 1];
                *(float2*)(C + (size_t)row * NDIM + col) =
                    make_float2(acc[mt][nt][0] + b0, acc[mt][nt][1] + b1);
                *(float2*)(C + (size_t)(row + 8) * NDIM + col) =
                    make_float2(acc[mt][nt][2] + b0, acc[mt][nt][3] + b1);
            } else if (z == 2) {
                *(uint2*)(C + (size_t)row * NDIM + col) =
                    make_uint2(f2tf32(acc[mt][nt][0]), f2tf32(acc[mt][nt][1]));
                *(uint2*)(C + (size_t)(row + 8) * NDIM + col) =
                    make_uint2(f2tf32(acc[mt][nt][2]), f2tf32(acc[mt][nt][3]));
            } else {
                *(float2*)(C + (size_t)row * NDIM + col) =
                    make_float2(acc[mt][nt][0], acc[mt][nt][1]);
                *(float2*)(C + (size_t)(row + 8) * NDIM + col) =
                    make_float2(acc[mt][nt][2], acc[mt][nt][3]);
            }
        }
    }
}

// ---------------------------------------------------------------------------
// RoPE in-place on Q and K; writes tf32-rounded values.
// ---------------------------------------------------------------------------
__global__ void __launch_bounds__(256) rope_kernel(float* __restrict__ Q,
                                                   float* __restrict__ Kt)
{
    int gid = blockIdx.x * blockDim.x + threadIdx.x;
    int m  = gid >> 9;
    int r  = gid & 511;
    int h  = r >> 5;
    int dd = r & 31;
    int i  = m & (NTOK - 1);

    float inv = exp2f(-(float)dd * (13.287712379549449f / 32.0f));
    float f = (float)i * inv;
    float c = cosf(f), s = sinf(f);

    size_t base = (size_t)m * INNER_ + h * DH_ + dd;
    float a = Q[base], b2 = Q[base + 32];
    Q[base]      = __uint_as_float(f2tf32(a * c - b2 * s));
    Q[base + 32] = __uint_as_float(f2tf32(b2 * c + a * s));
    a = Kt[base]; b2 = Kt[base + 32];
    Kt[base]      = __uint_as_float(f2tf32(a * c - b2 * s));
    Kt[base + 32] = __uint_as_float(f2tf32(b2 * c + a * s));
}

// ---------------------------------------------------------------------------
// Flash attention v2: 64-key chunks, cp.async K/V loads, dynamic smem.
// Block = (b,h,ti), 4 warps x 32 query rows. Masked temporal blocks skipped.
// smem words: K@0 (64x68=4352), V@4352 (64x72=4608), P@8960 (4x32x68=8704);
// total 17664 words = 70656 B.
// ---------------------------------------------------------------------------
#define A_KOFF 0
#define A_VOFF 4352
#define A_POFF 8960
#define A_KSTR 68
#define A_VSTR 72
#define A_PSTR 68
#define A_QSTR 68
#define A_SMEM_BYTES (17664 * 4)

__global__ void __launch_bounds__(128, 2) attn_mma_kernel(
    const float* __restrict__ Q, const float* __restrict__ K,
    const float* __restrict__ V, const int* __restrict__ tmask,
    float* __restrict__ O)
{
    extern __shared__ uint32_t sm[];

    int blk  = blockIdx.x;
    int ti   = blk % T_;
    int bh   = blk / T_;
    int h    = bh % H_;
    int b    = bh / H_;
    int tid  = threadIdx.x;
    int lane = tid & 31;
    int warp = tid >> 5;

    uint32_t smBase = (uint32_t)__cvta_generic_to_shared(sm);

    // stage Q tile 128x64 (raw bits already tf32); reuses K+V region
    {
        const float* qg = Q + ((size_t)(b * NTOK + ti * S_)) * INNER_ + h * DH_;
#pragma unroll
        for (int i = 0; i < 16; i++) {
            int idx = tid + i * 128;
            int row = idx >> 4, c4 = (idx & 15) * 4;
            float4 v4 = *(const float4*)(qg + (size_t)row * INNER_ + c4);
            *(uint4*)&sm[row * A_QSTR + c4] =
                make_uint4(__float_as_uint(v4.x), __float_as_uint(v4.y),
                           __float_as_uint(v4.z), __float_as_uint(v4.w));
        }
    }
    __syncthreads();

    uint32_t qf[2][8][4];
#pragma unroll
    for (int mt = 0; mt < 2; mt++)
#pragma unroll
        for (int kt = 0; kt < 8; kt++) {
            int r0 = warp * 32 + mt * 16 + (lane >> 2);
            int c  = kt * 8 + (lane & 3);
            qf[mt][kt][0] = sm[r0 * A_QSTR + c];
            qf[mt][kt][1] = sm[(r0 + 8) * A_QSTR + c];
            qf[mt][kt][2] = sm[r0 * A_QSTR + c + 4];
            qf[mt][kt][3] = sm[(r0 + 8) * A_QSTR + c + 4];
        }

    float of[2][8][4];
#pragma unroll
    for (int mt = 0; mt < 2; mt++)
#pragma unroll
        for (int nt = 0; nt < 8; nt++)
#pragma unroll
            for (int e = 0; e < 4; e++) of[mt][nt][e] = 0.f;
    float mx[2][2]  = {{-1e30f, -1e30f}, {-1e30f, -1e30f}};
    float ell[2][2] = {{0.f, 0.f}, {0.f, 0.f}};

    uint32_t pw = A_POFF + warp * (32 * A_PSTR);

    for (int tj = 0; tj < T_; tj++) {
        if (tmask[(b * T_ + ti) * T_ + tj] == 0) continue;
#pragma unroll 1
        for (int half = 0; half < 2; half++) {
            int j0 = tj * S_ + half * 64;
            const float* kb = K + ((size_t)(b * NTOK + j0)) * INNER_ + h * DH_;
            const float* vb = V + ((size_t)(b * NTOK + j0)) * INNER_ + h * DH_;
            __syncthreads();     // previous chunk's reads done
            // K and V tiles are 64 rows x 16 float4-chunks = 1024 chunks EACH
#pragma unroll
            for (int i = 0; i < 8; i++) {
                int q = tid + i * 128;        // 0..1023
                int row = q >> 4, c4 = (q & 15) * 4;
                cp16(smBase + (uint32_t)(A_KOFF + row * A_KSTR + c4) * 4,
                     kb + (size_t)row * INNER_ + c4);
                cp16(smBase + (uint32_t)(A_VOFF + row * A_VSTR + c4) * 4,
                     vb + (size_t)row * INNER_ + c4);
            }
            cp_commit();
            cp_wait<0>();
            __syncthreads();

            // S = Q * K^T (32 rows x 64 keys per warp)
            float sf[2][8][4];
#pragma unroll
            for (int mt = 0; mt < 2; mt++)
#pragma unroll
                for (int nt = 0; nt < 8; nt++)
#pragma unroll
                    for (int e = 0; e < 4; e++) sf[mt][nt][e] = 0.f;

#pragma unroll
            for (int kt = 0; kt < 8; kt++) {
                uint32_t bfr[8][2];
#pragma unroll
                for (int nt = 0; nt < 8; nt++) {
                    int n = nt * 8 + (lane >> 2);
                    int c = kt * 8 + (lane & 3);
                    bfr[nt][0] = sm[A_KOFF + n * A_KSTR + c];
                    bfr[nt][1] = sm[A_KOFF + n * A_KSTR + c + 4];
                }
#pragma unroll
                for (int mt = 0; mt < 2; mt++)
#pragma unroll
                    for (int nt = 0; nt < 8; nt++)
                        mma_tf32(sf[mt][nt], qf[mt][kt], bfr[nt]);
            }

            // online softmax over 64 keys
#pragma unroll
            for (int mt = 0; mt < 2; mt++) {
#pragma unroll
                for (int hh = 0; hh < 2; hh++) {
                    float cm = -1e30f;
#pragma unroll
                    for (int nt = 0; nt < 8; nt++) {
                        float s0 = sf[mt][nt][2 * hh]     * 0.125f;
                        float s1 = sf[mt][nt][2 * hh + 1] * 0.125f;
                        sf[mt][nt][2 * hh]     = s0;
                        sf[mt][nt][2 * hh + 1] = s1;
                        cm = fmaxf(cm, fmaxf(s0, s1));
                    }
                    cm = fmaxf(cm, __shfl_xor_sync(0xffffffffu, cm, 1));
                    cm = fmaxf(cm, __shfl_xor_sync(0xffffffffu, cm, 2));
                    float nm = fmaxf(mx[mt][hh], cm);
                    float corr = __expf(mx[mt][hh] - nm);
                    mx[mt][hh] = nm;
                    ell[mt][hh] *= corr;
#pragma unroll
                    for (int nt = 0; nt < 8; nt++) {
                        of[mt][nt][2 * hh]     *= corr;
                        of[mt][nt][2 * hh + 1] *= corr;
                    }
                    float rs = 0.f;
                    int rloc = mt * 16 + (lane >> 2) + hh * 8;
#pragma unroll
                    for (int nt = 0; nt < 8; nt++) {
                        float p0 = __expf(sf[mt][nt][2 * hh]     - nm);
                        float p1 = __expf(sf[mt][nt][2 * hh + 1] - nm);
                        rs += p0 + p1;
                        *(uint2*)&sm[pw + rloc * A_PSTR + nt * 8 + 2 * (lane & 3)] =
                            make_uint2(f2tf32(p0), f2tf32(p1));
                    }
                    rs += __shfl_xor_sync(0xffffffffu, rs, 1);
                    rs += __shfl_xor_sync(0xffffffffu, rs, 2);
                    ell[mt][hh] += rs;
                }
            }
            __syncwarp();

            // O += P * V (P: 32x64, V: 64x64)
#pragma unroll
            for (int kt = 0; kt < 8; kt++) {
                uint32_t pf[2][4];
#pragma unroll
                for (int mt = 0; mt < 2; mt++) {
                    int r0 = mt * 16 + (lane >> 2);
                    int c  = kt * 8 + (lane & 3);
                    pf[mt][0] = sm[pw + r0 * A_PSTR + c];
                    pf[mt][1] = sm[pw + (r0 + 8) * A_PSTR + c];
                    pf[mt][2] = sm[pw + r0 * A_PSTR + c + 4];
                    pf[mt][3] = sm[pw + (r0 + 8) * A_PSTR + c + 4];
                }
                uint32_t vf[8][2];
#pragma unroll
                for (int nt = 0; nt < 8; nt++) {
                    int n = nt * 8 + (lane >> 2);
                    int k = kt * 8 + (lane & 3);
                    vf[nt][0] = sm[A_VOFF + k * A_VSTR + n];
                    vf[nt][1] = sm[A_VOFF + (k + 4) * A_VSTR + n];
                }
#pragma unroll
                for (int mt = 0; mt < 2; mt++)
#pragma unroll
                    for (int nt = 0; nt < 8; nt++)
                        mma_tf32(of[mt][nt], pf[mt], vf[nt]);
            }
            __syncwarp();
        }
    }

    // normalize + tf32-round + write
#pragma unroll
    for (int mt = 0; mt < 2; mt++) {
#pragma unroll
        for (int hh = 0; hh < 2; hh++) {
            float inv = (ell[mt][hh] > 0.f) ? (1.f / ell[mt][hh]) : 0.f;
            int row = b * NTOK + ti * S_ + warp * 32 + mt * 16 + (lane >> 2) + hh * 8;
#pragma unroll
            for (int nt = 0; nt < 8; nt++) {
                int col = h * DH_ + nt * 8 + 2 * (lane & 3);
                *(uint2*)(O + (size_t)row * INNER_ + col) =
                    make_uint2(f2tf32(of[mt][nt][2 * hh] * inv),
                               f2tf32(of[mt][nt][2 * hh + 1] * inv));
            }
        }
    }
}

// ---------------------------------------------------------------------------
// Gate
// ---------------------------------------------------------------------------
__global__ void __launch_bounds__(128) gate_kernel(
    const float* __restrict__ P, const float* __restrict__ gw,
    const float* __restrict__ gb, float* __restrict__ out)
{
    int m = blockIdx.x;
    int tid = threadIdx.x;
    const float* row = P + (size_t)m * D_;

    float v[4];
    float part = 0.f;
#pragma unroll
    for (int r = 0; r < 4; r++) {
        int j = tid + r * 128;
        v[r] = row[j];
        part += v[r] * gw[j];
    }
#pragma unroll
    for (int off = 16; off; off >>= 1)
        part += __shfl_xor_sync(0xffffffffu, part, off);

    __shared__ float red[4];
    if ((tid & 31) == 0) red[tid >> 5] = part;
    __syncthreads();
    float tot = red[0] + red[1] + red[2] + red[3] + gb[0];
    float gate = 1.f / (1.f + __expf(-tot));

    float* orow = out + (size_t)m * D_;
#pragma unroll
    for (int r = 0; r < 4; r++) {
        int j = tid + r * 128;
        orow[j] = v[r] * gate;
    }
}

// ---------------------------------------------------------------------------
extern "C" void kernel_launch(void* const* d_in, const int* in_sizes, int n_in,
                              void* d_out, int out_size)
{
    (void)in_sizes; (void)n_in; (void)out_size;
    const float* x     = (const float*)d_in[0];
    const float* y     = (const float*)d_in[1];
    const int*   tmask = (const int*)  d_in[2];
    const float* Wq    = (const float*)d_in[3];
    const float* Wk    = (const float*)d_in[4];
    const float* Wv    = (const float*)d_in[5];
    const float* Wo    = (const float*)d_in[6];
    const float* bo    = (const float*)d_in[7];
    const float* pos   = (const float*)d_in[8];
    const float* gw    = (const float*)d_in[9];
    const float* gb    = (const float*)d_in[10];
    float* out = (float*)d_out;

    float *Qp, *Kp, *Vp, *Op, *Pp, *Wc;
    cudaGetSymbolAddress((void**)&Qp, g_Q);
    cudaGetSymbolAddress((void**)&Kp, g_K);
    cudaGetSymbolAddress((void**)&Vp, g_V);
    cudaGetSymbolAddress((void**)&Op, g_O);
    cudaGetSymbolAddress((void**)&Pp, g_P);
    cudaGetSymbolAddress((void**)&Wc, g_W);

    cudaFuncSetAttribute(gemm3_kernel<D_, INNER_, 0>,
                         cudaFuncAttributeMaxDynamicSharedMemorySize, G_SMEM_BYTES);
    cudaFuncSetAttribute(gemm3_kernel<INNER_, D_, 1>,
                         cudaFuncAttributeMaxDynamicSharedMemorySize, G_SMEM_BYTES);
    cudaFuncSetAttribute(attn_mma_kernel,
                         cudaFuncAttributeMaxDynamicSharedMemorySize, A_SMEM_BYTES);

    prep_xy_kernel<<<HALF_XY / 256, 256>>>(x, y, pos, Op, Op + HALF_XY);
    prep_w_kernel<<<(4 * WSEG) / 256, 256>>>(Wq, Wk, Wv, Wo, Wc);

    // QKV: [4096,1024] = xp/yp @ Wq/Wk/Wv
    dim3 gq(INNER_ / 128, MROWS / 128, 3);     // 8 x 32 x 3
    gemm3_kernel<D_, INNER_, 0><<<gq, 128, G_SMEM_BYTES>>>(
        Op, Wc, Qp, Kp, Vp, nullptr);

    rope_kernel<<<(MROWS * 512) / 256, 256>>>(Qp, Kp);

    attn_mma_kernel<<<B_ * H_ * T_, 128, A_SMEM_BYTES>>>(Qp, Kp, Vp, tmask, Op);

    // Proj: [4096,512] = O @ Wo + bo
    dim3 gp(D_ / 128, MROWS / 128, 1);         // 4 x 32
    gemm3_kernel<INNER_, D_, 1><<<gp, 128, G_SMEM_BYTES>>>(
        Op, Wc + 3 * WSEG, Pp, nullptr, nullptr, bo);

    gate_kernel<<<MROWS, 128>>>(Pp, gw, gb, out);
}